// round 14
// baseline (speedup 1.0000x reference)
#include <cuda_runtime.h>
#include <cuda_bf16.h>
#include <cstdint>

#define BB 8
#define TT 2048
#define DD 512
#define KC 32                       // bf16 k-chunk (elements) for pv
#define KC8 64                      // int8 k-chunk (elements) for qk
#define PITCHB 80                   // smem row pitch BYTES (64 data + 16 pad)
#define ARR (128 * PITCHB)          // one array: 10240 B
#define SB (4 * ARR)                // stage: 4 arrays = 40960 B
#define DYN_SMEM_PV (2 * SB)        // 81920 B -> 2 CTAs/SM
#define DYN_SMEM_QK (3 * SB)        // 122880 B -> 1 CTA/SM (reg-heavy anyway)

typedef __nv_bfloat16 bf16;

// ---------------- global scratch ----------------
__device__ __align__(1024) int8_t g_Qd0[(size_t)BB * TT * DD];
__device__ __align__(1024) int8_t g_Qd1[(size_t)BB * TT * DD];
__device__ __align__(1024) int8_t g_Kd0[(size_t)BB * TT * DD];
__device__ __align__(1024) int8_t g_Kd1[(size_t)BB * TT * DD];
__device__ __align__(1024) bf16 g_SThi[(size_t)BB * DD * TT];  // [b][d][t]
__device__ __align__(1024) bf16 g_STlo[(size_t)BB * DD * TT];
__device__ __align__(1024) bf16 g_Phi[(size_t)BB * TT * TT];
__device__ __align__(1024) bf16 g_Plo[(size_t)BB * TT * TT];
__device__ float g_part[(size_t)BB * TT * 64];
__device__ float g_sums[BB * TT];

// ---------------- PTX helpers (sm_80-era, legal on compute_103) ------------
__device__ __forceinline__ uint32_t smem_u32(const void* p) {
    uint32_t a;
    asm("{ .reg .u64 t; cvta.to.shared.u64 t, %1; cvt.u32.u64 %0, t; }" : "=r"(a) : "l"(p));
    return a;
}
__device__ __forceinline__ void cp16(uint32_t dst, const void* src) {
    asm volatile("cp.async.cg.shared.global [%0], [%1], 16;" :: "r"(dst), "l"(src) : "memory");
}
__device__ __forceinline__ void cp_commit() {
    asm volatile("cp.async.commit_group;" ::: "memory");
}
__device__ __forceinline__ void cp_wait1() {
    asm volatile("cp.async.wait_group 1;" ::: "memory");
}
__device__ __forceinline__ void cp_wait0() {
    asm volatile("cp.async.wait_group 0;" ::: "memory");
}
__device__ __forceinline__ void ldm_x4(uint32_t* d, uint32_t addr) {
    asm volatile("ldmatrix.sync.aligned.m8n8.x4.shared.b16 {%0,%1,%2,%3}, [%4];"
                 : "=r"(d[0]), "=r"(d[1]), "=r"(d[2]), "=r"(d[3]) : "r"(addr));
}
__device__ __forceinline__ void mma16816(float* c, const uint32_t* a, const uint32_t* b) {
    asm volatile(
        "mma.sync.aligned.m16n8k16.row.col.f32.bf16.bf16.f32 "
        "{%0,%1,%2,%3}, {%4,%5,%6,%7}, {%8,%9}, {%0,%1,%2,%3};"
        : "+f"(c[0]), "+f"(c[1]), "+f"(c[2]), "+f"(c[3])
        : "r"(a[0]), "r"(a[1]), "r"(a[2]), "r"(a[3]), "r"(b[0]), "r"(b[1]));
}
__device__ __forceinline__ void imma16832(int32_t* c, const uint32_t* a, const uint32_t* b) {
    asm volatile(
        "mma.sync.aligned.m16n8k32.row.col.s32.s8.s8.s32 "
        "{%0,%1,%2,%3}, {%4,%5,%6,%7}, {%8,%9}, {%0,%1,%2,%3};"
        : "+r"(c[0]), "+r"(c[1]), "+r"(c[2]), "+r"(c[3])
        : "r"(a[0]), "r"(a[1]), "r"(a[2]), "r"(a[3]), "r"(b[0]), "r"(b[1]));
}
__device__ __forceinline__ float ex2(float x) {
    float r;
    asm("ex2.approx.ftz.f32 %0, %1;" : "=f"(r) : "f"(x));
    return r;
}
__device__ __forceinline__ unsigned pk(bf16 a, bf16 b) {
    __nv_bfloat162 t = __halves2bfloat162(a, b);
    return *reinterpret_cast<unsigned*>(&t);
}

// ---------------- stage loaders: rows 0..127, 4x16B chunks per row ---------
__device__ __forceinline__ void ldstage_bf(uint32_t st,
                                           const bf16* ah, const bf16* al, size_t lda,
                                           const bf16* bh, const bf16* bl, size_t ldb,
                                           int k0, int tid) {
#pragma unroll
    for (int it = 0; it < 2; it++) {
        int f = tid + it * 256;
        int r = f >> 2, c = f & 3;
        uint32_t d = st + (uint32_t)(r * PITCHB + c * 16);
        size_t oa = (size_t)r * lda + k0 + c * 8;
        size_t ob = (size_t)r * ldb + k0 + c * 8;
        cp16(d,            ah + oa);
        cp16(d + ARR,      al + oa);
        cp16(d + 2 * ARR,  bh + ob);
        cp16(d + 3 * ARR,  bl + ob);
    }
}
__device__ __forceinline__ void ldstage_s8(uint32_t st,
                                           const int8_t* a0, const int8_t* a1,
                                           const int8_t* b0, const int8_t* b1,
                                           int k0, int tid) {
#pragma unroll
    for (int it = 0; it < 2; it++) {
        int f = tid + it * 256;
        int r = f >> 2, c = f & 3;
        uint32_t d = st + (uint32_t)(r * PITCHB + c * 16);
        size_t o = (size_t)r * DD + k0 + c * 16;   // int8: element == byte
        cp16(d,            a0 + o);
        cp16(d + ARR,      a1 + o);
        cp16(d + 2 * ARR,  b0 + o);
        cp16(d + 3 * ARR,  b1 + o);
    }
}

// ---------------- bf16 HMMA mainloop (pv; validated R10/R11) ---------------
__device__ __forceinline__ void gemm_main(const bf16* ah, const bf16* al, size_t lda,
                                          const bf16* bh, const bf16* bl, size_t ldb,
                                          int NC, uint32_t smem, float acc[4][4][4]) {
    const int tid = threadIdx.x;
    const int lane = tid & 31;
    const int wid = tid >> 5;
    const int wm = wid >> 2;
    const int wn = wid & 3;

#pragma unroll
    for (int mt = 0; mt < 4; mt++)
#pragma unroll
        for (int nt = 0; nt < 4; nt++)
#pragma unroll
            for (int u = 0; u < 4; u++) acc[mt][nt][u] = 0.f;

    const int arow = lane & 15;
    const int akc  = lane >> 4;
    const int brow = lane & 7;
    const int bkc  = (lane >> 3) & 1;
    const int bnt  = (lane >> 4) & 1;

    ldstage_bf(smem, ah, al, lda, bh, bl, ldb, 0, tid);
    cp_commit();

    for (int i = 0; i < NC; i++) {
        const int j = i + 1;
        if (j < NC) {
            ldstage_bf(smem + (j & 1) * SB, ah, al, lda, bh, bl, ldb, j * KC, tid);
            cp_commit();
            cp_wait1();
        } else {
            cp_wait0();
        }
        __syncthreads();

        const uint32_t sa = smem + (i & 1) * SB;
#pragma unroll
        for (int ks = 0; ks < 2; ks++) {
            uint32_t bfh[4][2], bfl[4][2];
#pragma unroll
            for (int np = 0; np < 2; np++) {
                uint32_t baddr = sa + 2 * ARR
                    + (uint32_t)((wn * 32 + (np * 2 + bnt) * 8 + brow) * PITCHB)
                    + (uint32_t)((ks * 2 + bkc) * 16);
                uint32_t t[4];
                ldm_x4(t, baddr);
                bfh[np * 2][0] = t[0]; bfh[np * 2][1] = t[1];
                bfh[np * 2 + 1][0] = t[2]; bfh[np * 2 + 1][1] = t[3];
                ldm_x4(t, baddr + ARR);
                bfl[np * 2][0] = t[0]; bfl[np * 2][1] = t[1];
                bfl[np * 2 + 1][0] = t[2]; bfl[np * 2 + 1][1] = t[3];
            }
#pragma unroll
            for (int mt = 0; mt < 4; mt++) {
                uint32_t aaddr = sa
                    + (uint32_t)((wm * 64 + mt * 16 + arow) * PITCHB)
                    + (uint32_t)((ks * 2 + akc) * 16);
                uint32_t afh[4], afl[4];
                ldm_x4(afh, aaddr);
                ldm_x4(afl, aaddr + ARR);
#pragma unroll
                for (int nt = 0; nt < 4; nt++) {
                    mma16816(acc[mt][nt], afh, bfh[nt]);
                    mma16816(acc[mt][nt], afh, bfl[nt]);
                    mma16816(acc[mt][nt], afl, bfh[nt]);
                }
            }
        }
        __syncthreads();
    }
}

// ---------------- K1: int8 2-digit IMMA; P~ -> bf16 hi/lo + partials -------
// x = s*d0 + s*d1/256 (s = 8/127). score = s^2*(acc_m + acc_c/256).
// acc_m: d0*d0. acc_c: d0*d1' + d1*d0' (same scale -> shared s32 acc).
__global__ __launch_bounds__(256, 1) void qk_kernel() {
    extern __shared__ char dyn_smem[];
    const uint32_t smem = smem_u32(dyn_smem);
    const int tid = threadIdx.x;
    const int lane = tid & 31;
    const int wid = tid >> 5;
    const int wm = wid >> 2, wn = wid & 3;
    const int q = lane & 3;
    const int b = blockIdx.z;
    const int tile_m = blockIdx.y * 128;
    const int tile_n = blockIdx.x * 128;

    const int8_t* qa0 = g_Qd0 + ((size_t)b * TT + tile_m) * DD;
    const int8_t* qa1 = g_Qd1 + ((size_t)b * TT + tile_m) * DD;
    const int8_t* kb0 = g_Kd0 + ((size_t)b * TT + tile_n) * DD;
    const int8_t* kb1 = g_Kd1 + ((size_t)b * TT + tile_n) * DD;

    int32_t accm[4][4][4], accc[4][4][4];
#pragma unroll
    for (int mt = 0; mt < 4; mt++)
#pragma unroll
        for (int nt = 0; nt < 4; nt++)
#pragma unroll
            for (int u = 0; u < 4; u++) { accm[mt][nt][u] = 0; accc[mt][nt][u] = 0; }

    const int arow = lane & 15;
    const int akc  = lane >> 4;
    const int brow = lane & 7;
    const int bkc  = (lane >> 3) & 1;
    const int bnt  = (lane >> 4) & 1;

    const int NC = DD / KC8;   // 8
    // 3-stage prologue
    ldstage_s8(smem, qa0, qa1, kb0, kb1, 0, tid);
    cp_commit();
    ldstage_s8(smem + SB, qa0, qa1, kb0, kb1, KC8, tid);
    cp_commit();

    for (int i = 0; i < NC; i++) {
        cp_wait1();
        __syncthreads();
        const int j = i + 2;
        if (j < NC)
            ldstage_s8(smem + (j % 3) * SB, qa0, qa1, kb0, kb1, j * KC8, tid);
        cp_commit();

        const uint32_t sa = smem + (i % 3) * SB;
#pragma unroll
        for (int ks = 0; ks < 2; ks++) {   // each ks = K32 = 32B half-row
            uint32_t b0[4][2], b1[4][2];
#pragma unroll
            for (int np = 0; np < 2; np++) {
                uint32_t baddr = sa + 2 * ARR
                    + (uint32_t)((wn * 32 + (np * 2 + bnt) * 8 + brow) * PITCHB)
                    + (uint32_t)(ks * 32 + bkc * 16);
                uint32_t t[4];
                ldm_x4(t, baddr);
                b0[np * 2][0] = t[0]; b0[np * 2][1] = t[1];
                b0[np * 2 + 1][0] = t[2]; b0[np * 2 + 1][1] = t[3];
                ldm_x4(t, baddr + ARR);
                b1[np * 2][0] = t[0]; b1[np * 2][1] = t[1];
                b1[np * 2 + 1][0] = t[2]; b1[np * 2 + 1][1] = t[3];
            }
#pragma unroll
            for (int mt = 0; mt < 4; mt++) {
                uint32_t aaddr = sa
                    + (uint32_t)((wm * 64 + mt * 16 + arow) * PITCHB)
                    + (uint32_t)(ks * 32 + akc * 16);
                uint32_t a0[4], a1[4];
                ldm_x4(a0, aaddr);
                ldm_x4(a1, aaddr + ARR);
#pragma unroll
                for (int nt = 0; nt < 4; nt++) {
                    imma16832(accm[mt][nt], a0, b0[nt]);
                    imma16832(accc[mt][nt], a0, b1[nt]);
                    imma16832(accc[mt][nt], a1, b0[nt]);
                }
            }
        }
        __syncthreads();
    }

    // score = s^2*(acc_m + acc_c/256); logit scale 1/sqrt(512); exp via exp2
    const float S8 = 8.0f / 127.0f;
    const float SCLM = S8 * S8 * 1.4426950408889634f * 0.04419417382415922f;
    const float SCLC = SCLM * (1.0f / 256.0f);
    bf16* Ph = g_Phi + (size_t)b * TT * TT;
    bf16* Pl = g_Plo + (size_t)b * TT * TT;
#pragma unroll
    for (int mt = 0; mt < 4; mt++) {
        const int r0 = tile_m + wm * 64 + mt * 16 + (lane >> 2);
        const int r1 = r0 + 8;
        float rs0 = 0.f, rs1 = 0.f;
#pragma unroll
        for (int nt = 0; nt < 4; nt++) {
            const int c0 = tile_n + wn * 32 + nt * 8 + q * 2;
            float p0 = ex2((float)accm[mt][nt][0] * SCLM + (float)accc[mt][nt][0] * SCLC);
            float p1 = ex2((float)accm[mt][nt][1] * SCLM + (float)accc[mt][nt][1] * SCLC);
            float p2 = ex2((float)accm[mt][nt][2] * SCLM + (float)accc[mt][nt][2] * SCLC);
            float p3 = ex2((float)accm[mt][nt][3] * SCLM + (float)accc[mt][nt][3] * SCLC);
            rs0 += p0 + p1;
            rs1 += p2 + p3;
            bf16 h0 = __float2bfloat16(p0), h1 = __float2bfloat16(p1);
            bf16 h2 = __float2bfloat16(p2), h3 = __float2bfloat16(p3);
            bf16 l0 = __float2bfloat16(p0 - __bfloat162float(h0));
            bf16 l1 = __float2bfloat16(p1 - __bfloat162float(h1));
            bf16 l2 = __float2bfloat16(p2 - __bfloat162float(h2));
            bf16 l3 = __float2bfloat16(p3 - __bfloat162float(h3));
            *reinterpret_cast<uint32_t*>(Ph + (size_t)r0 * TT + c0) = pk(h0, h1);
            *reinterpret_cast<uint32_t*>(Ph + (size_t)r1 * TT + c0) = pk(h2, h3);
            *reinterpret_cast<uint32_t*>(Pl + (size_t)r0 * TT + c0) = pk(l0, l1);
            *reinterpret_cast<uint32_t*>(Pl + (size_t)r1 * TT + c0) = pk(l2, l3);
        }
        rs0 += __shfl_xor_sync(0xFFFFFFFFu, rs0, 1);
        rs0 += __shfl_xor_sync(0xFFFFFFFFu, rs0, 2);
        rs1 += __shfl_xor_sync(0xFFFFFFFFu, rs1, 1);
        rs1 += __shfl_xor_sync(0xFFFFFFFFu, rs1, 2);
        if (q == 0) {
            const int col = blockIdx.x * 4 + wn;
            g_part[((size_t)b * TT + r0) * 64 + col] = rs0;
            g_part[((size_t)b * TT + r1) * 64 + col] = rs1;
        }
    }
}

// ---------------- reduce 64 partials per row -> g_sums ---------------------
__global__ __launch_bounds__(256) void sumpart_kernel() {
    const int row = blockIdx.x * 8 + (threadIdx.x >> 5);
    const int lane = threadIdx.x & 31;
    const float* p = g_part + (size_t)row * 64;
    float s = p[lane] + p[lane + 32];
#pragma unroll
    for (int o = 16; o; o >>= 1) s += __shfl_xor_sync(0xFFFFFFFFu, s, o);
    if (lane == 0) g_sums[row] = s;
}

// ---------------- K3: out = (P~ @ S) * V / rowsum (unchanged, validated) ---
__global__ __launch_bounds__(256, 2) void pv_kernel(const float* __restrict__ V,
                                                    float* __restrict__ Out) {
    extern __shared__ char dyn_smem[];
    const uint32_t smem = smem_u32(dyn_smem);
    const int tid = threadIdx.x;
    const int lane = tid & 31;
    const int wid = tid >> 5;
    const int wm = wid >> 2, wn = wid & 3;
    const int b = blockIdx.z;
    const int tile_m = blockIdx.y * 128;
    const int tile_n = blockIdx.x * 128;

    float acc[4][4][4];
    gemm_main(g_Phi + ((size_t)b * TT + tile_m) * TT,
              g_Plo + ((size_t)b * TT + tile_m) * TT, TT,
              g_SThi + ((size_t)b * DD + tile_n) * TT,
              g_STlo + ((size_t)b * DD + tile_n) * TT, TT,
              TT / KC, smem, acc);

    const float* Vb = V + (size_t)b * TT * DD;
    float* Ob = Out + (size_t)b * TT * DD;
    const float* sums = g_sums + b * TT;
#pragma unroll
    for (int mt = 0; mt < 4; mt++) {
        const int r0 = tile_m + wm * 64 + mt * 16 + (lane >> 2);
        const int r1 = r0 + 8;
        const float inv0 = 1.0f / sums[r0];
        const float inv1 = 1.0f / sums[r1];
#pragma unroll
        for (int nt = 0; nt < 4; nt++) {
            const int c0 = tile_n + wn * 32 + nt * 8 + (lane & 3) * 2;
            float2 v0 = *reinterpret_cast<const float2*>(Vb + (size_t)r0 * DD + c0);
            float2 v1 = *reinterpret_cast<const float2*>(Vb + (size_t)r1 * DD + c0);
            float2 o0, o1;
            o0.x = acc[mt][nt][0] * inv0 * v0.x;
            o0.y = acc[mt][nt][1] * inv0 * v0.y;
            o1.x = acc[mt][nt][2] * inv1 * v1.x;
            o1.y = acc[mt][nt][3] * inv1 * v1.y;
            *reinterpret_cast<float2*>(Ob + (size_t)r0 * DD + c0) = o0;
            *reinterpret_cast<float2*>(Ob + (size_t)r1 * DD + c0) = o1;
        }
    }
}

// ---------------- fp32 -> int8 2-digit conversion (Q, K) -------------------
// Destinations resolved IN DEVICE CODE (host-side __device__ symbol args give
// the host shadow address -> silent ATS writes to host memory; R4/R5 bug).
__global__ __launch_bounds__(256) void conv_q8_kernel(const float* __restrict__ src,
                                                      int which) {
    int8_t* d0a = (which == 0) ? g_Qd0 : g_Kd0;
    int8_t* d1a = (which == 0) ? g_Qd1 : g_Kd1;
    size_t i4 = (size_t)blockIdx.x * 256 + threadIdx.x;
    float4 v = reinterpret_cast<const float4*>(src)[i4];
    const float INV_S = 127.0f / 8.0f;
    char d0[4], d1[4];
    float xs[4] = {v.x, v.y, v.z, v.w};
#pragma unroll
    for (int u = 0; u < 4; u++) {
        float t = fminf(fmaxf(xs[u] * INV_S, -127.0f), 127.0f);
        int q0 = __float2int_rn(t);
        float r = (t - (float)q0) * 256.0f;
        int q1 = __float2int_rn(fminf(fmaxf(r, -127.0f), 127.0f));
        d0[u] = (char)q0;
        d1[u] = (char)q1;
    }
    reinterpret_cast<char4*>(d0a)[i4] = make_char4(d0[0], d0[1], d0[2], d0[3]);
    reinterpret_cast<char4*>(d1a)[i4] = make_char4(d1[0], d1[1], d1[2], d1[3]);
}

// transpose S[b][t][d] -> St[b][d][t] with hi/lo split (unchanged)
__global__ void conv_sT_kernel(const float* __restrict__ S) {
    __shared__ float t[32][33];
    const int b = blockIdx.z;
    const int t0 = blockIdx.x * 32, d0 = blockIdx.y * 32;
    const int x = threadIdx.x, y = threadIdx.y;
    const float* Sb = S + (size_t)b * TT * DD;
#pragma unroll
    for (int i = 0; i < 32; i += 8)
        t[y + i][x] = Sb[(size_t)(t0 + y + i) * DD + d0 + x];
    __syncthreads();
    bf16* Hb = g_SThi + (size_t)b * DD * TT;
    bf16* Lb = g_STlo + (size_t)b * DD * TT;
#pragma unroll
    for (int i = 0; i < 32; i += 8) {
        const int d = d0 + y + i;
        float v = t[x][y + i];
        bf16 h = __float2bfloat16(v);
        Hb[(size_t)d * TT + t0 + x] = h;
        Lb[(size_t)d * TT + t0 + x] = __float2bfloat16(v - __bfloat162float(h));
    }
}

// ---------------- host -----------------------------------------------------
extern "C" void kernel_launch(void* const* d_in, const int* in_sizes, int n_in,
                              void* d_out, int out_size) {
    const float* q = (const float*)d_in[0];
    const float* k = (const float*)d_in[1];
    const float* v = (const float*)d_in[2];
    const float* s = (const float*)d_in[3];
    float* out = (float*)d_out;

    cudaFuncSetAttribute(qk_kernel, cudaFuncAttributeMaxDynamicSharedMemorySize, DYN_SMEM_QK);
    cudaFuncSetAttribute(pv_kernel, cudaFuncAttributeMaxDynamicSharedMemorySize, DYN_SMEM_PV);

    const int n4 = BB * TT * DD / 4;
    conv_q8_kernel<<<n4 / 256, 256>>>(q, 0);
    conv_q8_kernel<<<n4 / 256, 256>>>(k, 1);
    conv_sT_kernel<<<dim3(TT / 32, DD / 32, BB), dim3(32, 8)>>>(s);

    qk_kernel<<<dim3(TT / 128, TT / 128, BB), 256, DYN_SMEM_QK>>>();
    sumpart_kernel<<<BB * TT / 8, 256>>>();
    pv_kernel<<<dim3(DD / 128, TT / 128, BB), 256, DYN_SMEM_PV>>>(v, out);
}

// round 15
// speedup vs baseline: 1.4688x; 1.4688x over previous
#include <cuda_runtime.h>
#include <cuda_bf16.h>
#include <cstdint>

#define BB 8
#define TT 2048
#define DD 512
#define KC 32                       // k-chunk (bf16 elements)
#define PITCHB 80                   // smem row pitch BYTES (64 data + 16 pad)
#define ARR (128 * PITCHB)          // one array: 10240 B
#define SB (4 * ARR)                // stage: Ah, Al, Bh, Bl = 40960 B
#define DYN_SMEM (3 * SB)           // 122880 B -> 1 CTA/SM, 3-stage pipeline

typedef __nv_bfloat16 bf16;

// ---------------- global scratch ----------------
__device__ __align__(1024) bf16 g_Qhi[(size_t)BB * TT * DD];
__device__ __align__(1024) bf16 g_Qlo[(size_t)BB * TT * DD];
__device__ __align__(1024) bf16 g_Khi[(size_t)BB * TT * DD];
__device__ __align__(1024) bf16 g_Klo[(size_t)BB * TT * DD];
__device__ __align__(1024) bf16 g_SThi[(size_t)BB * DD * TT];  // [b][d][t]
__device__ __align__(1024) bf16 g_STlo[(size_t)BB * DD * TT];
__device__ __align__(1024) bf16 g_Phi[(size_t)BB * TT * TT];
__device__ __align__(1024) bf16 g_Plo[(size_t)BB * TT * TT];
__device__ float g_part[(size_t)BB * TT * 64];
__device__ float g_sums[BB * TT];

// ---------------- PTX helpers (sm_80-era, legal on compute_103) ------------
__device__ __forceinline__ uint32_t smem_u32(const void* p) {
    uint32_t a;
    asm("{ .reg .u64 t; cvta.to.shared.u64 t, %1; cvt.u32.u64 %0, t; }" : "=r"(a) : "l"(p));
    return a;
}
__device__ __forceinline__ void cp16(uint32_t dst, const void* src) {
    asm volatile("cp.async.cg.shared.global [%0], [%1], 16;" :: "r"(dst), "l"(src) : "memory");
}
__device__ __forceinline__ void cp_commit() {
    asm volatile("cp.async.commit_group;" ::: "memory");
}
__device__ __forceinline__ void cp_wait1() {
    asm volatile("cp.async.wait_group 1;" ::: "memory");
}
__device__ __forceinline__ void ldm_x4(uint32_t* d, uint32_t addr) {
    asm volatile("ldmatrix.sync.aligned.m8n8.x4.shared.b16 {%0,%1,%2,%3}, [%4];"
                 : "=r"(d[0]), "=r"(d[1]), "=r"(d[2]), "=r"(d[3]) : "r"(addr));
}
__device__ __forceinline__ void mma16816(float* c, const uint32_t* a, const uint32_t* b) {
    asm volatile(
        "mma.sync.aligned.m16n8k16.row.col.f32.bf16.bf16.f32 "
        "{%0,%1,%2,%3}, {%4,%5,%6,%7}, {%8,%9}, {%0,%1,%2,%3};"
        : "+f"(c[0]), "+f"(c[1]), "+f"(c[2]), "+f"(c[3])
        : "r"(a[0]), "r"(a[1]), "r"(a[2]), "r"(a[3]), "r"(b[0]), "r"(b[1]));
}
__device__ __forceinline__ float ex2(float x) {
    float r;
    asm("ex2.approx.ftz.f32 %0, %1;" : "=f"(r) : "f"(x));
    return r;
}
__device__ __forceinline__ unsigned pk(bf16 a, bf16 b) {
    __nv_bfloat162 t = __halves2bfloat162(a, b);
    return *reinterpret_cast<unsigned*>(&t);
}

// ---------------- stage loader: rows 0..127, 4x16B chunks per row ----------
__device__ __forceinline__ void ldstage(uint32_t st,
                                        const bf16* ah, const bf16* al, size_t lda,
                                        const bf16* bh, const bf16* bl, size_t ldb,
                                        int k0, int tid) {
#pragma unroll
    for (int it = 0; it < 2; it++) {
        int f = tid + it * 256;
        int r = f >> 2, c = f & 3;
        uint32_t d = st + (uint32_t)(r * PITCHB + c * 16);
        size_t oa = (size_t)r * lda + k0 + c * 8;
        size_t ob = (size_t)r * ldb + k0 + c * 8;
        cp16(d,            ah + oa);
        cp16(d + ARR,      al + oa);
        cp16(d + 2 * ARR,  bh + ob);
        cp16(d + 3 * ARR,  bl + ob);
    }
}

// ---------------- bf16 HMMA mainloop: 3-stage, ONE sync per chunk ----------
// Datapath = R11 (validated, rel_err 1.07e-5). Loop structure = R14 (validated
// at 82.9% tensor): prologue 2 stages; per iter: wait(<=1 group) -> sync ->
// prefetch j=i+2 -> commit -> compute stage i%3.
__device__ __forceinline__ void gemm_main(const bf16* ah, const bf16* al, size_t lda,
                                          const bf16* bh, const bf16* bl, size_t ldb,
                                          int NC, uint32_t smem, float acc[4][4][4]) {
    const int tid = threadIdx.x;
    const int lane = tid & 31;
    const int wid = tid >> 5;
    const int wm = wid >> 2;
    const int wn = wid & 3;

#pragma unroll
    for (int mt = 0; mt < 4; mt++)
#pragma unroll
        for (int nt = 0; nt < 4; nt++)
#pragma unroll
            for (int u = 0; u < 4; u++) acc[mt][nt][u] = 0.f;

    const int arow = lane & 15;
    const int akc  = lane >> 4;
    const int brow = lane & 7;
    const int bkc  = (lane >> 3) & 1;
    const int bnt  = (lane >> 4) & 1;

    ldstage(smem, ah, al, lda, bh, bl, ldb, 0, tid);
    cp_commit();
    ldstage(smem + SB, ah, al, lda, bh, bl, ldb, KC, tid);
    cp_commit();

    for (int i = 0; i < NC; i++) {
        cp_wait1();
        __syncthreads();
        const int j = i + 2;
        if (j < NC)
            ldstage(smem + (j % 3) * SB, ah, al, lda, bh, bl, ldb, j * KC, tid);
        cp_commit();

        const uint32_t sa = smem + (i % 3) * SB;
#pragma unroll
        for (int ks = 0; ks < 2; ks++) {
            uint32_t bfh[4][2], bfl[4][2];
#pragma unroll
            for (int np = 0; np < 2; np++) {
                uint32_t baddr = sa + 2 * ARR
                    + (uint32_t)((wn * 32 + (np * 2 + bnt) * 8 + brow) * PITCHB)
                    + (uint32_t)((ks * 2 + bkc) * 16);
                uint32_t t[4];
                ldm_x4(t, baddr);
                bfh[np * 2][0] = t[0]; bfh[np * 2][1] = t[1];
                bfh[np * 2 + 1][0] = t[2]; bfh[np * 2 + 1][1] = t[3];
                ldm_x4(t, baddr + ARR);
                bfl[np * 2][0] = t[0]; bfl[np * 2][1] = t[1];
                bfl[np * 2 + 1][0] = t[2]; bfl[np * 2 + 1][1] = t[3];
            }
#pragma unroll
            for (int mt = 0; mt < 4; mt++) {
                uint32_t aaddr = sa
                    + (uint32_t)((wm * 64 + mt * 16 + arow) * PITCHB)
                    + (uint32_t)((ks * 2 + akc) * 16);
                uint32_t afh[4], afl[4];
                ldm_x4(afh, aaddr);
                ldm_x4(afl, aaddr + ARR);
#pragma unroll
                for (int nt = 0; nt < 4; nt++) {
                    mma16816(acc[mt][nt], afh, bfh[nt]);
                    mma16816(acc[mt][nt], afh, bfl[nt]);
                    mma16816(acc[mt][nt], afl, bfh[nt]);
                }
            }
        }
    }
}

// ---------------- K1: P~ = exp(QK^T * scale) -> bf16 hi/lo + partials ------
__global__ __launch_bounds__(256, 1) void qk_kernel() {
    extern __shared__ char dyn_smem[];
    const uint32_t smem = smem_u32(dyn_smem);
    const int tid = threadIdx.x;
    const int lane = tid & 31;
    const int wid = tid >> 5;
    const int wm = wid >> 2, wn = wid & 3;
    const int q = lane & 3;
    const int b = blockIdx.z;
    const int tile_m = blockIdx.y * 128;
    const int tile_n = blockIdx.x * 128;

    float acc[4][4][4];
    gemm_main(g_Qhi + ((size_t)b * TT + tile_m) * DD,
              g_Qlo + ((size_t)b * TT + tile_m) * DD, DD,
              g_Khi + ((size_t)b * TT + tile_n) * DD,
              g_Klo + ((size_t)b * TT + tile_n) * DD, DD,
              DD / KC, smem, acc);

    const float SCL = 1.4426950408889634f * 0.04419417382415922f;
    bf16* Ph = g_Phi + (size_t)b * TT * TT;
    bf16* Pl = g_Plo + (size_t)b * TT * TT;
#pragma unroll
    for (int mt = 0; mt < 4; mt++) {
        const int r0 = tile_m + wm * 64 + mt * 16 + (lane >> 2);
        const int r1 = r0 + 8;
        float rs0 = 0.f, rs1 = 0.f;
#pragma unroll
        for (int nt = 0; nt < 4; nt++) {
            const int c0 = tile_n + wn * 32 + nt * 8 + q * 2;
            float p0 = ex2(acc[mt][nt][0] * SCL);
            float p1 = ex2(acc[mt][nt][1] * SCL);
            float p2 = ex2(acc[mt][nt][2] * SCL);
            float p3 = ex2(acc[mt][nt][3] * SCL);
            rs0 += p0 + p1;
            rs1 += p2 + p3;
            bf16 h0 = __float2bfloat16(p0), h1 = __float2bfloat16(p1);
            bf16 h2 = __float2bfloat16(p2), h3 = __float2bfloat16(p3);
            bf16 l0 = __float2bfloat16(p0 - __bfloat162float(h0));
            bf16 l1 = __float2bfloat16(p1 - __bfloat162float(h1));
            bf16 l2 = __float2bfloat16(p2 - __bfloat162float(h2));
            bf16 l3 = __float2bfloat16(p3 - __bfloat162float(h3));
            *reinterpret_cast<uint32_t*>(Ph + (size_t)r0 * TT + c0) = pk(h0, h1);
            *reinterpret_cast<uint32_t*>(Ph + (size_t)r1 * TT + c0) = pk(h2, h3);
            *reinterpret_cast<uint32_t*>(Pl + (size_t)r0 * TT + c0) = pk(l0, l1);
            *reinterpret_cast<uint32_t*>(Pl + (size_t)r1 * TT + c0) = pk(l2, l3);
        }
        rs0 += __shfl_xor_sync(0xFFFFFFFFu, rs0, 1);
        rs0 += __shfl_xor_sync(0xFFFFFFFFu, rs0, 2);
        rs1 += __shfl_xor_sync(0xFFFFFFFFu, rs1, 1);
        rs1 += __shfl_xor_sync(0xFFFFFFFFu, rs1, 2);
        if (q == 0) {
            const int col = blockIdx.x * 4 + wn;
            g_part[((size_t)b * TT + r0) * 64 + col] = rs0;
            g_part[((size_t)b * TT + r1) * 64 + col] = rs1;
        }
    }
}

// ---------------- reduce 64 partials per row -> g_sums ---------------------
__global__ __launch_bounds__(256) void sumpart_kernel() {
    const int row = blockIdx.x * 8 + (threadIdx.x >> 5);
    const int lane = threadIdx.x & 31;
    const float* p = g_part + (size_t)row * 64;
    float s = p[lane] + p[lane + 32];
#pragma unroll
    for (int o = 16; o; o >>= 1) s += __shfl_xor_sync(0xFFFFFFFFu, s, o);
    if (lane == 0) g_sums[row] = s;
}

// ---------------- K3: out = (P~ @ S) * V / rowsum --------------------------
__global__ __launch_bounds__(256, 1) void pv_kernel(const float* __restrict__ V,
                                                    float* __restrict__ Out) {
    extern __shared__ char dyn_smem[];
    const uint32_t smem = smem_u32(dyn_smem);
    const int tid = threadIdx.x;
    const int lane = tid & 31;
    const int wid = tid >> 5;
    const int wm = wid >> 2, wn = wid & 3;
    const int b = blockIdx.z;
    const int tile_m = blockIdx.y * 128;
    const int tile_n = blockIdx.x * 128;

    float acc[4][4][4];
    gemm_main(g_Phi + ((size_t)b * TT + tile_m) * TT,
              g_Plo + ((size_t)b * TT + tile_m) * TT, TT,
              g_SThi + ((size_t)b * DD + tile_n) * TT,
              g_STlo + ((size_t)b * DD + tile_n) * TT, TT,
              TT / KC, smem, acc);

    const float* Vb = V + (size_t)b * TT * DD;
    float* Ob = Out + (size_t)b * TT * DD;
    const float* sums = g_sums + b * TT;
#pragma unroll
    for (int mt = 0; mt < 4; mt++) {
        const int r0 = tile_m + wm * 64 + mt * 16 + (lane >> 2);
        const int r1 = r0 + 8;
        const float inv0 = 1.0f / sums[r0];
        const float inv1 = 1.0f / sums[r1];
#pragma unroll
        for (int nt = 0; nt < 4; nt++) {
            const int c0 = tile_n + wn * 32 + nt * 8 + (lane & 3) * 2;
            float2 v0 = *reinterpret_cast<const float2*>(Vb + (size_t)r0 * DD + c0);
            float2 v1 = *reinterpret_cast<const float2*>(Vb + (size_t)r1 * DD + c0);
            float2 o0, o1;
            o0.x = acc[mt][nt][0] * inv0 * v0.x;
            o0.y = acc[mt][nt][1] * inv0 * v0.y;
            o1.x = acc[mt][nt][2] * inv1 * v1.x;
            o1.y = acc[mt][nt][3] * inv1 * v1.y;
            *reinterpret_cast<float2*>(Ob + (size_t)r0 * DD + c0) = o0;
            *reinterpret_cast<float2*>(Ob + (size_t)r1 * DD + c0) = o1;
        }
    }
}

// ---------------- fp32 -> bf16 hi/lo conversions ---------------------------
// Destinations resolved IN DEVICE CODE (host-side __device__ symbol args give
// the host shadow address -> silent ATS writes to host memory; R4/R5 bug).
__global__ __launch_bounds__(256) void conv_hl_kernel(const float* __restrict__ src,
                                                      int which) {
    bf16* hi = (which == 0) ? g_Qhi : g_Khi;
    bf16* lo = (which == 0) ? g_Qlo : g_Klo;
    size_t i4 = (size_t)blockIdx.x * 256 + threadIdx.x;
    float4 v = reinterpret_cast<const float4*>(src)[i4];
    bf16 h0 = __float2bfloat16(v.x), h1 = __float2bfloat16(v.y);
    bf16 h2 = __float2bfloat16(v.z), h3 = __float2bfloat16(v.w);
    bf16 l0 = __float2bfloat16(v.x - __bfloat162float(h0));
    bf16 l1 = __float2bfloat16(v.y - __bfloat162float(h1));
    bf16 l2 = __float2bfloat16(v.z - __bfloat162float(h2));
    bf16 l3 = __float2bfloat16(v.w - __bfloat162float(h3));
    reinterpret_cast<uint2*>(hi)[i4] = make_uint2(pk(h0, h1), pk(h2, h3));
    reinterpret_cast<uint2*>(lo)[i4] = make_uint2(pk(l0, l1), pk(l2, l3));
}

// transpose S[b][t][d] -> St[b][d][t] with hi/lo split
__global__ void conv_sT_kernel(const float* __restrict__ S) {
    __shared__ float t[32][33];
    const int b = blockIdx.z;
    const int t0 = blockIdx.x * 32, d0 = blockIdx.y * 32;
    const int x = threadIdx.x, y = threadIdx.y;
    const float* Sb = S + (size_t)b * TT * DD;
#pragma unroll
    for (int i = 0; i < 32; i += 8)
        t[y + i][x] = Sb[(size_t)(t0 + y + i) * DD + d0 + x];
    __syncthreads();
    bf16* Hb = g_SThi + (size_t)b * DD * TT;
    bf16* Lb = g_STlo + (size_t)b * DD * TT;
#pragma unroll
    for (int i = 0; i < 32; i += 8) {
        const int d = d0 + y + i;
        float v = t[x][y + i];
        bf16 h = __float2bfloat16(v);
        Hb[(size_t)d * TT + t0 + x] = h;
        Lb[(size_t)d * TT + t0 + x] = __float2bfloat16(v - __bfloat162float(h));
    }
}

// ---------------- host -----------------------------------------------------
extern "C" void kernel_launch(void* const* d_in, const int* in_sizes, int n_in,
                              void* d_out, int out_size) {
    const float* q = (const float*)d_in[0];
    const float* k = (const float*)d_in[1];
    const float* v = (const float*)d_in[2];
    const float* s = (const float*)d_in[3];
    float* out = (float*)d_out;

    cudaFuncSetAttribute(qk_kernel, cudaFuncAttributeMaxDynamicSharedMemorySize, DYN_SMEM);
    cudaFuncSetAttribute(pv_kernel, cudaFuncAttributeMaxDynamicSharedMemorySize, DYN_SMEM);

    const int n4 = BB * TT * DD / 4;
    conv_hl_kernel<<<n4 / 256, 256>>>(q, 0);
    conv_hl_kernel<<<n4 / 256, 256>>>(k, 1);
    conv_sT_kernel<<<dim3(TT / 32, DD / 32, BB), dim3(32, 8)>>>(s);

    qk_kernel<<<dim3(TT / 128, TT / 128, BB), 256, DYN_SMEM>>>();
    sumpart_kernel<<<BB * TT / 8, 256>>>();
    pv_kernel<<<dim3(DD / 128, TT / 128, BB), 256, DYN_SMEM>>>(v, out);
}

// round 17
// speedup vs baseline: 1.8164x; 1.2367x over previous
#include <cuda_runtime.h>
#include <cuda_bf16.h>
#include <cstdint>

#define BB 8
#define TT 2048
#define DD 512
#define KC 32                       // k-chunk (bf16 elements)
#define ARR 8192                    // one array: 128 rows * 64 B (swizzled)
#define SB (4 * ARR)                // stage: Ah, Al, Bh, Bl = 32768 B
#define DYN_SMEM (2 * SB)           // 65536 B -> 2 CTAs/SM @ 512 thr
#define NTHR 512

typedef __nv_bfloat16 bf16;

// ---------------- global scratch ----------------
__device__ __align__(1024) bf16 g_Qhi[(size_t)BB * TT * DD];
__device__ __align__(1024) bf16 g_Qlo[(size_t)BB * TT * DD];
__device__ __align__(1024) bf16 g_Khi[(size_t)BB * TT * DD];
__device__ __align__(1024) bf16 g_Klo[(size_t)BB * TT * DD];
__device__ __align__(1024) bf16 g_SThi[(size_t)BB * DD * TT];  // [b][d][t]
__device__ __align__(1024) bf16 g_STlo[(size_t)BB * DD * TT];
__device__ __align__(1024) bf16 g_Phi[(size_t)BB * TT * TT];
__device__ __align__(1024) bf16 g_Plo[(size_t)BB * TT * TT];
__device__ float g_part[(size_t)BB * TT * 64];
__device__ float g_sums[BB * TT];

// ---------------- PTX helpers (sm_80-era, legal on compute_103) ------------
__device__ __forceinline__ uint32_t smem_u32(const void* p) {
    uint32_t a;
    asm("{ .reg .u64 t; cvta.to.shared.u64 t, %1; cvt.u32.u64 %0, t; }" : "=r"(a) : "l"(p));
    return a;
}
__device__ __forceinline__ void cp16(uint32_t dst, const void* src) {
    asm volatile("cp.async.cg.shared.global [%0], [%1], 16;" :: "r"(dst), "l"(src) : "memory");
}
__device__ __forceinline__ void cp_commit() {
    asm volatile("cp.async.commit_group;" ::: "memory");
}
__device__ __forceinline__ void cp_wait1() {
    asm volatile("cp.async.wait_group 1;" ::: "memory");
}
__device__ __forceinline__ void cp_wait0() {
    asm volatile("cp.async.wait_group 0;" ::: "memory");
}
__device__ __forceinline__ void ldm_x4(uint32_t* d, uint32_t addr) {
    asm volatile("ldmatrix.sync.aligned.m8n8.x4.shared.b16 {%0,%1,%2,%3}, [%4];"
                 : "=r"(d[0]), "=r"(d[1]), "=r"(d[2]), "=r"(d[3]) : "r"(addr));
}
__device__ __forceinline__ void mma16816(float* c, const uint32_t* a, const uint32_t* b) {
    asm volatile(
        "mma.sync.aligned.m16n8k16.row.col.f32.bf16.bf16.f32 "
        "{%0,%1,%2,%3}, {%4,%5,%6,%7}, {%8,%9}, {%0,%1,%2,%3};"
        : "+f"(c[0]), "+f"(c[1]), "+f"(c[2]), "+f"(c[3])
        : "r"(a[0]), "r"(a[1]), "r"(a[2]), "r"(a[3]), "r"(b[0]), "r"(b[1]));
}
__device__ __forceinline__ float ex2(float x) {
    float r;
    asm("ex2.approx.ftz.f32 %0, %1;" : "=f"(r) : "f"(x));
    return r;
}
__device__ __forceinline__ unsigned pk(bf16 a, bf16 b) {
    __nv_bfloat162 t = __halves2bfloat162(a, b);
    return *reinterpret_cast<unsigned*>(&t);
}
// swizzled smem offset: row r (64B rows), 16B-granule c (0..3)
__device__ __forceinline__ uint32_t swz(int r, int c) {
    return (uint32_t)(r * 64 + ((c ^ ((r >> 1) & 3)) << 4));
}

// ---------------- stage loader: 512 threads, 1 cp16 x 4 arrays each --------
__device__ __forceinline__ void ldstage(uint32_t st,
                                        const bf16* ah, const bf16* al, size_t lda,
                                        const bf16* bh, const bf16* bl, size_t ldb,
                                        int k0, int tid) {
    int r = tid >> 2, c = tid & 3;
    uint32_t d = st + swz(r, c);
    size_t oa = (size_t)r * lda + k0 + c * 8;
    size_t ob = (size_t)r * ldb + k0 + c * 8;
    cp16(d,            ah + oa);
    cp16(d + ARR,      al + oa);
    cp16(d + 2 * ARR,  bh + ob);
    cp16(d + 3 * ARR,  bl + ob);
}

// ---------------- HMMA mainloop: 16 warps, 32x32 warp tile, 3-term split ---
// Datapath math identical to R11 (validated). Swizzle layout (validated
// indirectly: R4/R5 identical-error proof). acc = 32 regs/thread.
__device__ __forceinline__ void gemm_main(const bf16* ah, const bf16* al, size_t lda,
                                          const bf16* bh, const bf16* bl, size_t ldb,
                                          int NC, uint32_t smem, float acc[2][4][4]) {
    const int tid = threadIdx.x;
    const int lane = tid & 31;
    const int wid = tid >> 5;
    const int wm = wid >> 2;      // 0..3 -> 32-row band
    const int wn = wid & 3;       // 0..3 -> 32-col band

#pragma unroll
    for (int mt = 0; mt < 2; mt++)
#pragma unroll
        for (int nt = 0; nt < 4; nt++)
#pragma unroll
            for (int u = 0; u < 4; u++) acc[mt][nt][u] = 0.f;

    const int arow = lane & 15;
    const int akc  = lane >> 4;
    const int brow = lane & 7;
    const int bkc  = (lane >> 3) & 1;
    const int bnt  = (lane >> 4) & 1;

    ldstage(smem, ah, al, lda, bh, bl, ldb, 0, tid);
    cp_commit();

    for (int i = 0; i < NC; i++) {
        const int j = i + 1;
        if (j < NC) {
            ldstage(smem + (j & 1) * SB, ah, al, lda, bh, bl, ldb, j * KC, tid);
            cp_commit();
            cp_wait1();
        } else {
            cp_wait0();
        }
        __syncthreads();

        const uint32_t sa = smem + (i & 1) * SB;
#pragma unroll
        for (int ks = 0; ks < 2; ks++) {
            // hoist A fragments (2 mt, hi+lo): 4 x4 = 16 regs
            uint32_t afh[2][4], afl[2][4];
#pragma unroll
            for (int mt = 0; mt < 2; mt++) {
                int row = wm * 32 + mt * 16 + arow;
                uint32_t aaddr = sa + swz(row, ks * 2 + akc);
                ldm_x4(afh[mt], aaddr);
                ldm_x4(afl[mt], aaddr + ARR);
            }
            // stream B per nt-pair: 2 x4 live (8 regs)
#pragma unroll
            for (int np = 0; np < 2; np++) {
                int rowb = wn * 32 + (np * 2 + bnt) * 8 + brow;
                uint32_t baddr = sa + 2 * ARR + swz(rowb, ks * 2 + bkc);
                uint32_t th[4], tl[4];
                ldm_x4(th, baddr);
                ldm_x4(tl, baddr + ARR);
#pragma unroll
                for (int half = 0; half < 2; half++) {
                    const int nt = np * 2 + half;
                    const uint32_t bh2[2] = {th[half * 2], th[half * 2 + 1]};
                    const uint32_t bl2[2] = {tl[half * 2], tl[half * 2 + 1]};
#pragma unroll
                    for (int mt = 0; mt < 2; mt++) {
                        mma16816(acc[mt][nt], afh[mt], bh2);
                        mma16816(acc[mt][nt], afh[mt], bl2);
                        mma16816(acc[mt][nt], afl[mt], bh2);
                    }
                }
            }
        }
        __syncthreads();
    }
}

// ---------------- K1: P~ = exp(QK^T * scale) -> bf16 hi/lo + partials ------
__global__ __launch_bounds__(NTHR, 2) void qk_kernel() {
    extern __shared__ char dyn_smem[];
    const uint32_t smem = smem_u32(dyn_smem);
    const int tid = threadIdx.x;
    const int lane = tid & 31;
    const int wid = tid >> 5;
    const int wm = wid >> 2, wn = wid & 3;
    const int q = lane & 3;
    const int b = blockIdx.z;
    const int tile_m = blockIdx.y * 128;
    const int tile_n = blockIdx.x * 128;

    float acc[2][4][4];
    gemm_main(g_Qhi + ((size_t)b * TT + tile_m) * DD,
              g_Qlo + ((size_t)b * TT + tile_m) * DD, DD,
              g_Khi + ((size_t)b * TT + tile_n) * DD,
              g_Klo + ((size_t)b * TT + tile_n) * DD, DD,
              DD / KC, smem, acc);

    const float SCL = 1.4426950408889634f * 0.04419417382415922f;
    bf16* Ph = g_Phi + (size_t)b * TT * TT;
    bf16* Pl = g_Plo + (size_t)b * TT * TT;
#pragma unroll
    for (int mt = 0; mt < 2; mt++) {
        const int r0 = tile_m + wm * 32 + mt * 16 + (lane >> 2);
        const int r1 = r0 + 8;
        float rs0 = 0.f, rs1 = 0.f;
#pragma unroll
        for (int nt = 0; nt < 4; nt++) {
            const int c0 = tile_n + wn * 32 + nt * 8 + q * 2;
            float p0 = ex2(acc[mt][nt][0] * SCL);
            float p1 = ex2(acc[mt][nt][1] * SCL);
            float p2 = ex2(acc[mt][nt][2] * SCL);
            float p3 = ex2(acc[mt][nt][3] * SCL);
            rs0 += p0 + p1;
            rs1 += p2 + p3;
            bf16 h0 = __float2bfloat16(p0), h1 = __float2bfloat16(p1);
            bf16 h2 = __float2bfloat16(p2), h3 = __float2bfloat16(p3);
            bf16 l0 = __float2bfloat16(p0 - __bfloat162float(h0));
            bf16 l1 = __float2bfloat16(p1 - __bfloat162float(h1));
            bf16 l2 = __float2bfloat16(p2 - __bfloat162float(h2));
            bf16 l3 = __float2bfloat16(p3 - __bfloat162float(h3));
            *reinterpret_cast<uint32_t*>(Ph + (size_t)r0 * TT + c0) = pk(h0, h1);
            *reinterpret_cast<uint32_t*>(Ph + (size_t)r1 * TT + c0) = pk(h2, h3);
            *reinterpret_cast<uint32_t*>(Pl + (size_t)r0 * TT + c0) = pk(l0, l1);
            *reinterpret_cast<uint32_t*>(Pl + (size_t)r1 * TT + c0) = pk(l2, l3);
        }
        rs0 += __shfl_xor_sync(0xFFFFFFFFu, rs0, 1);
        rs0 += __shfl_xor_sync(0xFFFFFFFFu, rs0, 2);
        rs1 += __shfl_xor_sync(0xFFFFFFFFu, rs1, 1);
        rs1 += __shfl_xor_sync(0xFFFFFFFFu, rs1, 2);
        if (q == 0) {
            const int col = blockIdx.x * 4 + wn;
            g_part[((size_t)b * TT + r0) * 64 + col] = rs0;
            g_part[((size_t)b * TT + r1) * 64 + col] = rs1;
        }
    }
}

// ---------------- reduce 64 partials per row -> g_sums ---------------------
__global__ __launch_bounds__(256) void sumpart_kernel() {
    const int row = blockIdx.x * 8 + (threadIdx.x >> 5);
    const int lane = threadIdx.x & 31;
    const float* p = g_part + (size_t)row * 64;
    float s = p[lane] + p[lane + 32];
#pragma unroll
    for (int o = 16; o; o >>= 1) s += __shfl_xor_sync(0xFFFFFFFFu, s, o);
    if (lane == 0) g_sums[row] = s;
}

// ---------------- K3: out = (P~ @ S) * V / rowsum --------------------------
__global__ __launch_bounds__(NTHR, 2) void pv_kernel(const float* __restrict__ V,
                                                     float* __restrict__ Out) {
    extern __shared__ char dyn_smem[];
    const uint32_t smem = smem_u32(dyn_smem);
    const int tid = threadIdx.x;
    const int lane = tid & 31;
    const int wid = tid >> 5;
    const int wm = wid >> 2, wn = wid & 3;
    const int b = blockIdx.z;
    const int tile_m = blockIdx.y * 128;
    const int tile_n = blockIdx.x * 128;

    float acc[2][4][4];
    gemm_main(g_Phi + ((size_t)b * TT + tile_m) * TT,
              g_Plo + ((size_t)b * TT + tile_m) * TT, TT,
              g_SThi + ((size_t)b * DD + tile_n) * TT,
              g_STlo + ((size_t)b * DD + tile_n) * TT, TT,
              TT / KC, smem, acc);

    const float* Vb = V + (size_t)b * TT * DD;
    float* Ob = Out + (size_t)b * TT * DD;
    const float* sums = g_sums + b * TT;
#pragma unroll
    for (int mt = 0; mt < 2; mt++) {
        const int r0 = tile_m + wm * 32 + mt * 16 + (lane >> 2);
        const int r1 = r0 + 8;
        const float inv0 = 1.0f / sums[r0];
        const float inv1 = 1.0f / sums[r1];
#pragma unroll
        for (int nt = 0; nt < 4; nt++) {
            const int c0 = tile_n + wn * 32 + nt * 8 + (lane & 3) * 2;
            float2 v0 = *reinterpret_cast<const float2*>(Vb + (size_t)r0 * DD + c0);
            float2 v1 = *reinterpret_cast<const float2*>(Vb + (size_t)r1 * DD + c0);
            float2 o0, o1;
            o0.x = acc[mt][nt][0] * inv0 * v0.x;
            o0.y = acc[mt][nt][1] * inv0 * v0.y;
            o1.x = acc[mt][nt][2] * inv1 * v1.x;
            o1.y = acc[mt][nt][3] * inv1 * v1.y;
            *reinterpret_cast<float2*>(Ob + (size_t)r0 * DD + c0) = o0;
            *reinterpret_cast<float2*>(Ob + (size_t)r1 * DD + c0) = o1;
        }
    }
}

// ---------------- fp32 -> bf16 hi/lo conversions ---------------------------
// Destinations resolved IN DEVICE CODE (host-side __device__ symbol args give
// the host shadow address -> silent ATS writes to host memory; R4/R5 bug).
__global__ __launch_bounds__(256) void conv_hl_kernel(const float* __restrict__ src,
                                                      int which) {
    bf16* hi = (which == 0) ? g_Qhi : g_Khi;
    bf16* lo = (which == 0) ? g_Qlo : g_Klo;
    size_t i4 = (size_t)blockIdx.x * 256 + threadIdx.x;
    float4 v = reinterpret_cast<const float4*>(src)[i4];
    bf16 h0 = __float2bfloat16(v.x), h1 = __float2bfloat16(v.y);
    bf16 h2 = __float2bfloat16(v.z), h3 = __float2bfloat16(v.w);
    bf16 l0 = __float2bfloat16(v.x - __bfloat162float(h0));
    bf16 l1 = __float2bfloat16(v.y - __bfloat162float(h1));
    bf16 l2 = __float2bfloat16(v.z - __bfloat162float(h2));
    bf16 l3 = __float2bfloat16(v.w - __bfloat162float(h3));
    reinterpret_cast<uint2*>(hi)[i4] = make_uint2(pk(h0, h1), pk(h2, h3));
    reinterpret_cast<uint2*>(lo)[i4] = make_uint2(pk(l0, l1), pk(l2, l3));
}

// transpose S[b][t][d] -> St[b][d][t] with hi/lo split
__global__ void conv_sT_kernel(const float* __restrict__ S) {
    __shared__ float t[32][33];
    const int b = blockIdx.z;
    const int t0 = blockIdx.x * 32, d0 = blockIdx.y * 32;
    const int x = threadIdx.x, y = threadIdx.y;
    const float* Sb = S + (size_t)b * TT * DD;
#pragma unroll
    for (int i = 0; i < 32; i += 8)
        t[y + i][x] = Sb[(size_t)(t0 + y + i) * DD + d0 + x];
    __syncthreads();
    bf16* Hb = g_SThi + (size_t)b * DD * TT;
    bf16* Lb = g_STlo + (size_t)b * DD * TT;
#pragma unroll
    for (int i = 0; i < 32; i += 8) {
        const int d = d0 + y + i;
        float v = t[x][y + i];
        bf16 h = __float2bfloat16(v);
        Hb[(size_t)d * TT + t0 + x] = h;
        Lb[(size_t)d * TT + t0 + x] = __float2bfloat16(v - __bfloat162float(h));
    }
}

// ---------------- host -----------------------------------------------------
extern "C" void kernel_launch(void* const* d_in, const int* in_sizes, int n_in,
                              void* d_out, int out_size) {
    const float* q = (const float*)d_in[0];
    const float* k = (const float*)d_in[1];
    const float* v = (const float*)d_in[2];
    const float* s = (const float*)d_in[3];
    float* out = (float*)d_out;

    cudaFuncSetAttribute(qk_kernel, cudaFuncAttributeMaxDynamicSharedMemorySize, DYN_SMEM);
    cudaFuncSetAttribute(pv_kernel, cudaFuncAttributeMaxDynamicSharedMemorySize, DYN_SMEM);

    const int n4 = BB * TT * DD / 4;
    conv_hl_kernel<<<n4 / 256, 256>>>(q, 0);
    conv_hl_kernel<<<n4 / 256, 256>>>(k, 1);
    conv_sT_kernel<<<dim3(TT / 32, DD / 32, BB), dim3(32, 8)>>>(s);

    qk_kernel<<<dim3(TT / 128, TT / 128, BB), NTHR, DYN_SMEM>>>();
    sumpart_kernel<<<BB * TT / 8, 256>>>();
    pv_kernel<<<dim3(DD / 128, TT / 128, BB), NTHR, DYN_SMEM>>>(v, out);
}